// round 1
// baseline (speedup 1.0000x reference)
#include <cuda_runtime.h>
#include <math.h>

// ---------------- problem constants ----------------
#define B_  2
#define S_  4096
#define D_  768
#define H_  12
#define DH_ 64
#define L_  2
#define F_  3072
#define C_  256
#define M_  (B_*S_)           // 8192 rows
#define NEGV (-1000000000.0f)

// ---------------- scratch (static device mem; no allocs allowed) ----------------
__device__ float g_h  [M_ * D_];
__device__ float g_q  [M_ * D_];
__device__ float g_k  [M_ * D_];
__device__ float g_v  [M_ * D_];
__device__ float g_ctx[M_ * D_];
__device__ float g_t  [M_ * D_];
__device__ float g_f  [M_ * F_];

// ---------------- reductions ----------------
__device__ __forceinline__ float warp_sum(float v) {
    #pragma unroll
    for (int o = 16; o; o >>= 1) v += __shfl_xor_sync(0xffffffffu, v, o);
    return v;
}
__device__ __forceinline__ float warp_max(float v) {
    #pragma unroll
    for (int o = 16; o; o >>= 1) v = fmaxf(v, __shfl_xor_sync(0xffffffffu, v, o));
    return v;
}
__device__ float block_sum(float v, float* red) {
    int lane = threadIdx.x & 31, w = threadIdx.x >> 5;
    v = warp_sum(v);
    __syncthreads();                 // protect red reuse
    if (lane == 0) red[w] = v;
    __syncthreads();
    int nw = (blockDim.x + 31) >> 5;
    float r = (threadIdx.x < nw) ? red[threadIdx.x] : 0.0f;
    if (w == 0) { r = warp_sum(r); if (lane == 0) red[0] = r; }
    __syncthreads();
    return red[0];
}
__device__ float block_max(float v, float* red) {
    int lane = threadIdx.x & 31, w = threadIdx.x >> 5;
    v = warp_max(v);
    __syncthreads();
    if (lane == 0) red[w] = v;
    __syncthreads();
    int nw = (blockDim.x + 31) >> 5;
    float r = (threadIdx.x < nw) ? red[threadIdx.x] : -INFINITY;
    if (w == 0) { r = warp_max(r); if (lane == 0) red[0] = r; }
    __syncthreads();
    return red[0];
}

// ---------------- embedding + layernorm ----------------
// grid = M_, block = 256 (D_=768 -> 3 elems/thread)
__global__ void embed_ln_kernel(const int* __restrict__ ids,
                                const float* __restrict__ tok,
                                const float* __restrict__ pos,
                                const float* __restrict__ g,
                                const float* __restrict__ be,
                                float* __restrict__ out) {
    __shared__ float red[32];
    int row = blockIdx.x;
    int s = row % S_;
    int id = ids[row];
    const float* tp = tok + (size_t)id * D_;
    const float* pp = pos + (size_t)s  * D_;
    float vals[3]; float lsum = 0.0f;
    #pragma unroll
    for (int i = 0; i < 3; i++) {
        int c = threadIdx.x + i * 256;
        vals[i] = tp[c] + pp[c];
        lsum += vals[i];
    }
    float mean = block_sum(lsum, red) * (1.0f / D_);
    float lv = 0.0f;
    #pragma unroll
    for (int i = 0; i < 3; i++) { float d = vals[i] - mean; lv += d * d; }
    float var = block_sum(lv, red) * (1.0f / D_);
    float inv = rsqrtf(var + 1e-5f);
    float* op = out + (size_t)row * D_;
    #pragma unroll
    for (int i = 0; i < 3; i++) {
        int c = threadIdx.x + i * 256;
        op[c] = (vals[i] - mean) * inv * g[c] + be[c];
    }
}

// ---------------- residual add + layernorm ----------------
__global__ void add_ln_kernel(const float* __restrict__ x,
                              const float* __restrict__ r,
                              const float* __restrict__ g,
                              const float* __restrict__ be,
                              float* __restrict__ out) {
    __shared__ float red[32];
    int row = blockIdx.x;
    const float* xp = x + (size_t)row * D_;
    const float* rp = r + (size_t)row * D_;
    float vals[3]; float lsum = 0.0f;
    #pragma unroll
    for (int i = 0; i < 3; i++) {
        int c = threadIdx.x + i * 256;
        vals[i] = xp[c] + rp[c];
        lsum += vals[i];
    }
    float mean = block_sum(lsum, red) * (1.0f / D_);
    float lv = 0.0f;
    #pragma unroll
    for (int i = 0; i < 3; i++) { float d = vals[i] - mean; lv += d * d; }
    float var = block_sum(lv, red) * (1.0f / D_);
    float inv = rsqrtf(var + 1e-5f);
    float* op = out + (size_t)row * D_;
    #pragma unroll
    for (int i = 0; i < 3; i++) {
        int c = threadIdx.x + i * 256;
        op[c] = (vals[i] - mean) * inv * g[c] + be[c];
    }
}

// ---------------- fp32 tiled GEMM: C = act((A[M,K] @ W[K,N] + bias) * scale) ----------------
// BM=BN=128, BK=16, 256 threads, 8x8 per thread. M%128==0, N%128==0, K%16==0.
#define GBM 128
#define GBN 128
#define GBK 16
__global__ __launch_bounds__(256) void gemm_bias_kernel(
        const float* __restrict__ A, const float* __restrict__ W,
        const float* __restrict__ bias, float* __restrict__ Co,
        int M, int N, int K, int act, float scale) {
    __shared__ float As[GBK][GBM];
    __shared__ float Bs[GBK][GBN];
    int tid = threadIdx.x;
    int tx = tid & 15, ty = tid >> 4;
    int rowBase = blockIdx.y * GBM;
    int colBase = blockIdx.x * GBN;

    int aRow  = tid >> 2;       // 0..63, two passes (+64)
    int aCol4 = tid & 3;        // 4 float4 per 16-wide row
    int bRow  = tid >> 5;       // 0..7, two passes (+8)
    int bCol4 = tid & 31;       // 32 float4 per 128-wide row

    float acc[8][8];
    #pragma unroll
    for (int i = 0; i < 8; i++)
        #pragma unroll
        for (int j = 0; j < 8; j++) acc[i][j] = 0.0f;

    for (int k0 = 0; k0 < K; k0 += GBK) {
        #pragma unroll
        for (int p = 0; p < 2; p++) {
            int r = aRow + p * 64;
            float4 v = *(const float4*)&A[(size_t)(rowBase + r) * K + k0 + aCol4 * 4];
            As[aCol4 * 4 + 0][r] = v.x;
            As[aCol4 * 4 + 1][r] = v.y;
            As[aCol4 * 4 + 2][r] = v.z;
            As[aCol4 * 4 + 3][r] = v.w;
        }
        #pragma unroll
        for (int p = 0; p < 2; p++) {
            int r = bRow + p * 8;
            *(float4*)&Bs[r][bCol4 * 4] =
                *(const float4*)&W[(size_t)(k0 + r) * N + colBase + bCol4 * 4];
        }
        __syncthreads();
        #pragma unroll
        for (int kk = 0; kk < GBK; kk++) {
            float a[8], b[8];
            *(float4*)&a[0] = *(float4*)&As[kk][ty * 8];
            *(float4*)&a[4] = *(float4*)&As[kk][ty * 8 + 4];
            *(float4*)&b[0] = *(float4*)&Bs[kk][tx * 8];
            *(float4*)&b[4] = *(float4*)&Bs[kk][tx * 8 + 4];
            #pragma unroll
            for (int i = 0; i < 8; i++)
                #pragma unroll
                for (int j = 0; j < 8; j++)
                    acc[i][j] = fmaf(a[i], b[j], acc[i][j]);
        }
        __syncthreads();
    }

    #pragma unroll
    for (int i = 0; i < 8; i++) {
        int r = rowBase + ty * 8 + i;
        #pragma unroll
        for (int j = 0; j < 8; j += 4) {
            float4 o;
            float* po = &o.x;
            #pragma unroll
            for (int q = 0; q < 4; q++) {
                int c = colBase + tx * 8 + j + q;
                float val = (acc[i][j + q] + bias[c]) * scale;
                if (act == 1) val = 0.5f * val * (1.0f + erff(val * 0.70710678118654752f));
                po[q] = val;
            }
            *(float4*)&Co[(size_t)r * N + colBase + tx * 8 + j] = o;
        }
    }
}

// ---------------- sliding-window attention: one block per (b,h,query) ----------------
// grid = (S_, H_, B_), 128 threads. Layout of q/k/v/ctx: [B,S,D] with head h at cols h*64..h*64+63.
__global__ void sw_attn_kernel(const float* __restrict__ q,
                               const float* __restrict__ k,
                               const float* __restrict__ v,
                               const int* __restrict__ mask,
                               float* __restrict__ ctx) {
    __shared__ float qs[64];
    __shared__ float sc[3 * C_ + 3];
    __shared__ float red[32];
    __shared__ float cpart[128];
    int i = blockIdx.x, h = blockIdx.y, b = blockIdx.z;
    int tid = threadIdx.x;
    int n = i / C_, c = i % C_;
    const float* qp = q + ((size_t)(b * S_ + i)) * D_ + h * DH_;
    if (tid < 16) ((float4*)qs)[tid] = ((const float4*)qp)[tid];
    __syncthreads();

    int j0 = (n - 1) * C_;
    for (int kk = tid; kk < 3 * C_; kk += 128) {
        int j = j0 + kk;
        float s = NEGV;
        if (kk >= c && kk <= c + 2 * C_ && j > 0 && j < S_ && mask[b * S_ + j] > 0) {
            const float4* kp = (const float4*)(k + ((size_t)(b * S_ + j)) * D_ + h * DH_);
            float acc = 0.0f;
            #pragma unroll
            for (int d4 = 0; d4 < 16; d4++) {
                float4 kv = kp[d4];
                float4 qv = ((const float4*)qs)[d4];
                acc += kv.x * qv.x + kv.y * qv.y + kv.z * qv.z + kv.w * qv.w;
            }
            s = acc;
        }
        sc[kk] = s;
    }
    if (tid == 0) {  // global-token score q_i . k_0
        float s = NEGV;
        if (mask[b * S_] > 0) {
            const float* kp = k + ((size_t)(b * S_)) * D_ + h * DH_;
            float acc = 0.0f;
            #pragma unroll
            for (int d = 0; d < 64; d++) acc += qs[d] * kp[d];
            s = acc;
        }
        sc[3 * C_] = s;
    }
    __syncthreads();

    float m = -INFINITY;
    for (int kk = tid; kk < 3 * C_ + 1; kk += 128) m = fmaxf(m, sc[kk]);
    m = block_max(m, red);
    float lsum = 0.0f;
    for (int kk = tid; kk < 3 * C_ + 1; kk += 128) {
        float e = expf(sc[kk] - m);
        sc[kk] = e;
        lsum += e;
    }
    float sum = block_sum(lsum, red);
    float inv = 1.0f / sum;

    int d = tid & 63, part = tid >> 6;   // 2 parts
    float accum = 0.0f;
    for (int kk = part; kk < 3 * C_; kk += 2) {
        int j = j0 + kk;
        if (j >= 0 && j < S_)
            accum += sc[kk] * v[((size_t)(b * S_ + j)) * D_ + h * DH_ + d];
    }
    if (part == 0)
        accum += sc[3 * C_] * v[((size_t)(b * S_)) * D_ + h * DH_ + d];
    cpart[tid] = accum;
    __syncthreads();
    if (part == 0)
        ctx[((size_t)(b * S_ + i)) * D_ + h * DH_ + d] = (cpart[d] + cpart[64 + d]) * inv;
}

// ---------------- full attention for query row 0: one block per (b,h) ----------------
// grid = (H_, B_), 256 threads. Overwrites ctx row 0.
__global__ void global_attn_kernel(const float* __restrict__ q,
                                   const float* __restrict__ k,
                                   const float* __restrict__ v,
                                   const int* __restrict__ mask,
                                   float* __restrict__ ctx) {
    __shared__ float qs[64];
    __shared__ float sc[S_];
    __shared__ float red[32];
    __shared__ float cpart[256];
    int h = blockIdx.x, b = blockIdx.y;
    int tid = threadIdx.x;
    const float* qp = q + ((size_t)(b * S_)) * D_ + h * DH_;
    if (tid < 16) ((float4*)qs)[tid] = ((const float4*)qp)[tid];
    __syncthreads();

    for (int j = tid; j < S_; j += 256) {
        float s = NEGV;
        if (mask[b * S_ + j] > 0) {
            const float4* kp = (const float4*)(k + ((size_t)(b * S_ + j)) * D_ + h * DH_);
            float acc = 0.0f;
            #pragma unroll
            for (int d4 = 0; d4 < 16; d4++) {
                float4 kv = kp[d4];
                float4 qv = ((const float4*)qs)[d4];
                acc += kv.x * qv.x + kv.y * qv.y + kv.z * qv.z + kv.w * qv.w;
            }
            s = acc;
        }
        sc[j] = s;
    }
    __syncthreads();

    float m = -INFINITY;
    for (int j = tid; j < S_; j += 256) m = fmaxf(m, sc[j]);
    m = block_max(m, red);
    float lsum = 0.0f;
    for (int j = tid; j < S_; j += 256) {
        float e = expf(sc[j] - m);
        sc[j] = e;
        lsum += e;
    }
    float sum = block_sum(lsum, red);
    float inv = 1.0f / sum;

    int d = tid & 63, part = tid >> 6;  // 4 parts
    float accum = 0.0f;
    for (int j = part; j < S_; j += 4)
        accum += sc[j] * v[((size_t)(b * S_ + j)) * D_ + h * DH_ + d];
    cpart[tid] = accum;
    __syncthreads();
    if (part == 0)
        ctx[((size_t)(b * S_)) * D_ + h * DH_ + d] =
            (cpart[d] + cpart[64 + d] + cpart[128 + d] + cpart[192 + d]) * inv;
}

// ---------------- classifier head: logits[b][c] = h[b,0,:] @ cls_W + cls_b ----------------
__global__ void cls_kernel(const float* __restrict__ h,
                           const float* __restrict__ W,
                           const float* __restrict__ bias,
                           float* __restrict__ out) {
    int w = threadIdx.x >> 5, lane = threadIdx.x & 31;
    if (w < B_ * 3) {
        int b = w / 3, c = w % 3;
        float acc = 0.0f;
        for (int kx = lane; kx < D_; kx += 32)
            acc += h[((size_t)(b * S_)) * D_ + kx] * W[kx * 3 + c];
        acc = warp_sum(acc);
        if (lane == 0) out[b * 3 + c] = acc + bias[c];
    }
}

// ---------------- launch ----------------
extern "C" void kernel_launch(void* const* d_in, const int* in_sizes, int n_in,
                              void* d_out, int out_size) {
    const int*   ids      = (const int*)d_in[0];
    const int*   mask     = (const int*)d_in[1];
    const float* emb_tok  = (const float*)d_in[2];
    const float* emb_pos  = (const float*)d_in[3];
    const float* emb_ln_g = (const float*)d_in[4];
    const float* emb_ln_b = (const float*)d_in[5];
    const float* Wq = (const float*)d_in[6];
    const float* bq = (const float*)d_in[7];
    const float* Wk = (const float*)d_in[8];
    const float* bk = (const float*)d_in[9];
    const float* Wv = (const float*)d_in[10];
    const float* bv = (const float*)d_in[11];
    const float* Wo = (const float*)d_in[12];
    const float* bo = (const float*)d_in[13];
    const float* ln1_g = (const float*)d_in[14];
    const float* ln1_b = (const float*)d_in[15];
    const float* W1 = (const float*)d_in[16];
    const float* b1 = (const float*)d_in[17];
    const float* W2 = (const float*)d_in[18];
    const float* b2 = (const float*)d_in[19];
    const float* ln2_g = (const float*)d_in[20];
    const float* ln2_b = (const float*)d_in[21];
    const float* clsW = (const float*)d_in[22];
    const float* clsb = (const float*)d_in[23];

    float *h, *q, *k, *v, *ctx, *t, *f;
    cudaGetSymbolAddress((void**)&h,   g_h);
    cudaGetSymbolAddress((void**)&q,   g_q);
    cudaGetSymbolAddress((void**)&k,   g_k);
    cudaGetSymbolAddress((void**)&v,   g_v);
    cudaGetSymbolAddress((void**)&ctx, g_ctx);
    cudaGetSymbolAddress((void**)&t,   g_t);
    cudaGetSymbolAddress((void**)&f,   g_f);

    embed_ln_kernel<<<M_, 256>>>(ids, emb_tok, emb_pos, emb_ln_g, emb_ln_b, h);

    for (int l = 0; l < L_; l++) {
        const float* Wql = Wq + (size_t)l * D_ * D_;
        const float* Wkl = Wk + (size_t)l * D_ * D_;
        const float* Wvl = Wv + (size_t)l * D_ * D_;
        const float* Wol = Wo + (size_t)l * D_ * D_;
        const float* W1l = W1 + (size_t)l * D_ * F_;
        const float* W2l = W2 + (size_t)l * F_ * D_;

        dim3 gD(D_ / GBN, M_ / GBM);
        dim3 gF(F_ / GBN, M_ / GBM);

        gemm_bias_kernel<<<gD, 256>>>(h, Wql, bq + l * D_, q, M_, D_, D_, 0, 0.125f);
        gemm_bias_kernel<<<gD, 256>>>(h, Wkl, bk + l * D_, k, M_, D_, D_, 0, 1.0f);
        gemm_bias_kernel<<<gD, 256>>>(h, Wvl, bv + l * D_, v, M_, D_, D_, 0, 1.0f);

        sw_attn_kernel<<<dim3(S_, H_, B_), 128>>>(q, k, v, mask, ctx);
        global_attn_kernel<<<dim3(H_, B_), 256>>>(q, k, v, mask, ctx);

        gemm_bias_kernel<<<gD, 256>>>(ctx, Wol, bo + l * D_, t, M_, D_, D_, 0, 1.0f);
        add_ln_kernel<<<M_, 256>>>(h, t, ln1_g + l * D_, ln1_b + l * D_, h);

        gemm_bias_kernel<<<gF, 256>>>(h, W1l, b1 + l * F_, f, M_, F_, D_, 1, 1.0f);
        gemm_bias_kernel<<<gD, 256>>>(f, W2l, b2 + l * D_, t, M_, D_, F_, 0, 1.0f);
        add_ln_kernel<<<M_, 256>>>(h, t, ln2_g + l * D_, ln2_b + l * D_, h);
    }

    cls_kernel<<<1, 256>>>(h, clsW, clsb, (float*)d_out);
}

// round 2
// speedup vs baseline: 2.7480x; 2.7480x over previous
#include <cuda_runtime.h>
#include <math.h>

// ---------------- problem constants ----------------
#define B_  2
#define S_  4096
#define D_  768
#define H_  12
#define DH_ 64
#define L_  2
#define F_  3072
#define C_  256
#define M_  (B_*S_)           // 8192 rows
#define NEGV (-1000000000.0f)

// ---------------- scratch (static device mem; no allocs allowed) ----------------
__device__ float g_h  [M_ * D_];
__device__ float g_q  [M_ * D_];
__device__ float g_k  [M_ * D_];
__device__ float g_v  [M_ * D_];
__device__ float g_ctx[M_ * D_];
__device__ float g_t  [M_ * D_];
__device__ float g_f  [M_ * F_];

// ---------------- reductions ----------------
__device__ __forceinline__ float warp_sum(float v) {
    #pragma unroll
    for (int o = 16; o; o >>= 1) v += __shfl_xor_sync(0xffffffffu, v, o);
    return v;
}
__device__ __forceinline__ float warp_max(float v) {
    #pragma unroll
    for (int o = 16; o; o >>= 1) v = fmaxf(v, __shfl_xor_sync(0xffffffffu, v, o));
    return v;
}
__device__ float block_sum(float v, float* red) {
    int lane = threadIdx.x & 31, w = threadIdx.x >> 5;
    v = warp_sum(v);
    __syncthreads();
    if (lane == 0) red[w] = v;
    __syncthreads();
    int nw = (blockDim.x + 31) >> 5;
    float r = (threadIdx.x < nw) ? red[threadIdx.x] : 0.0f;
    if (w == 0) { r = warp_sum(r); if (lane == 0) red[0] = r; }
    __syncthreads();
    return red[0];
}
__device__ float block_max(float v, float* red) {
    int lane = threadIdx.x & 31, w = threadIdx.x >> 5;
    v = warp_max(v);
    __syncthreads();
    if (lane == 0) red[w] = v;
    __syncthreads();
    int nw = (blockDim.x + 31) >> 5;
    float r = (threadIdx.x < nw) ? red[threadIdx.x] : -INFINITY;
    if (w == 0) { r = warp_max(r); if (lane == 0) red[0] = r; }
    __syncthreads();
    return red[0];
}

// ---------------- embedding + layernorm ----------------
__global__ void embed_ln_kernel(const int* __restrict__ ids,
                                const float* __restrict__ tok,
                                const float* __restrict__ pos,
                                const float* __restrict__ g,
                                const float* __restrict__ be,
                                float* __restrict__ out) {
    __shared__ float red[32];
    int row = blockIdx.x;
    int s = row % S_;
    int id = ids[row];
    const float* tp = tok + (size_t)id * D_;
    const float* pp = pos + (size_t)s  * D_;
    float vals[3]; float lsum = 0.0f;
    #pragma unroll
    for (int i = 0; i < 3; i++) {
        int c = threadIdx.x + i * 256;
        vals[i] = tp[c] + pp[c];
        lsum += vals[i];
    }
    float mean = block_sum(lsum, red) * (1.0f / D_);
    float lv = 0.0f;
    #pragma unroll
    for (int i = 0; i < 3; i++) { float d = vals[i] - mean; lv += d * d; }
    float var = block_sum(lv, red) * (1.0f / D_);
    float inv = rsqrtf(var + 1e-5f);
    float* op = out + (size_t)row * D_;
    #pragma unroll
    for (int i = 0; i < 3; i++) {
        int c = threadIdx.x + i * 256;
        op[c] = (vals[i] - mean) * inv * g[c] + be[c];
    }
}

// ---------------- residual add + layernorm ----------------
__global__ void add_ln_kernel(const float* __restrict__ x,
                              const float* __restrict__ r,
                              const float* __restrict__ g,
                              const float* __restrict__ be,
                              float* __restrict__ out) {
    __shared__ float red[32];
    int row = blockIdx.x;
    const float* xp = x + (size_t)row * D_;
    const float* rp = r + (size_t)row * D_;
    float vals[3]; float lsum = 0.0f;
    #pragma unroll
    for (int i = 0; i < 3; i++) {
        int c = threadIdx.x + i * 256;
        vals[i] = xp[c] + rp[c];
        lsum += vals[i];
    }
    float mean = block_sum(lsum, red) * (1.0f / D_);
    float lv = 0.0f;
    #pragma unroll
    for (int i = 0; i < 3; i++) { float d = vals[i] - mean; lv += d * d; }
    float var = block_sum(lv, red) * (1.0f / D_);
    float inv = rsqrtf(var + 1e-5f);
    float* op = out + (size_t)row * D_;
    #pragma unroll
    for (int i = 0; i < 3; i++) {
        int c = threadIdx.x + i * 256;
        op[c] = (vals[i] - mean) * inv * g[c] + be[c];
    }
}

// ---------------- tf32 mma GEMM: C = act((A[M,K] @ W[K,N] + bias) * scale) ----------------
#define TBM 128
#define TBN 128
#define TBK 16
#define ASTR 20
#define BSTR 132

__device__ __forceinline__ unsigned f2tf(float v) {
    unsigned r; asm("cvt.rna.tf32.f32 %0, %1;" : "=r"(r) : "f"(v)); return r;
}

__device__ __forceinline__ void mma_tf32(float* c, const unsigned* a, const unsigned* b) {
    asm volatile(
        "mma.sync.aligned.m16n8k8.row.col.f32.tf32.tf32.f32 "
        "{%0,%1,%2,%3},{%4,%5,%6,%7},{%8,%9},{%0,%1,%2,%3};\n"
        : "+f"(c[0]), "+f"(c[1]), "+f"(c[2]), "+f"(c[3])
        : "r"(a[0]), "r"(a[1]), "r"(a[2]), "r"(a[3]), "r"(b[0]), "r"(b[1]));
}

__global__ __launch_bounds__(256) void gemm_tf32_kernel(
        const float* __restrict__ A, const float* __restrict__ W,
        const float* __restrict__ bias, float* __restrict__ Co,
        int M, int N, int K, int act, float scale) {
    __shared__ float As[2][TBM * ASTR];
    __shared__ float Bs[2][TBK * BSTR];

    int tid = threadIdx.x;
    int lane = tid & 31, wid = tid >> 5;
    int wm = (wid & 3) * 32;      // warp row offset within tile
    int wn = (wid >> 2) * 64;     // warp col offset within tile
    int gid = lane >> 2, tig = lane & 3;
    size_t rowBase = (size_t)blockIdx.y * TBM;
    size_t colBase = (size_t)blockIdx.x * TBN;

    // global load slots
    int s0 = tid, s1 = tid + 256;
    int ar0 = s0 >> 2, ac0 = (s0 & 3) * 4;
    int ar1 = s1 >> 2, ac1 = (s1 & 3) * 4;
    int br0 = s0 >> 5, bc0 = (s0 & 31) * 4;
    int br1 = s1 >> 5, bc1 = (s1 & 31) * 4;

    float c[2][8][4];
    #pragma unroll
    for (int mi = 0; mi < 2; mi++)
        #pragma unroll
        for (int ni = 0; ni < 8; ni++)
            #pragma unroll
            for (int q = 0; q < 4; q++) c[mi][ni][q] = 0.0f;

    int ntiles = K / TBK;

    float4 aPre0, aPre1, bPre0, bPre1;
    aPre0 = *(const float4*)&A[(rowBase + ar0) * K + ac0];
    aPre1 = *(const float4*)&A[(rowBase + ar1) * K + ac1];
    bPre0 = *(const float4*)&W[(size_t)br0 * N + colBase + bc0];
    bPre1 = *(const float4*)&W[(size_t)br1 * N + colBase + bc1];
    *(float4*)&As[0][ar0 * ASTR + ac0] = aPre0;
    *(float4*)&As[0][ar1 * ASTR + ac1] = aPre1;
    *(float4*)&Bs[0][br0 * BSTR + bc0] = bPre0;
    *(float4*)&Bs[0][br1 * BSTR + bc1] = bPre1;
    __syncthreads();

    for (int kt = 0; kt < ntiles; kt++) {
        int cur = kt & 1;
        bool hasNext = (kt + 1) < ntiles;
        if (hasNext) {
            int k0 = (kt + 1) * TBK;
            aPre0 = *(const float4*)&A[(rowBase + ar0) * K + k0 + ac0];
            aPre1 = *(const float4*)&A[(rowBase + ar1) * K + k0 + ac1];
            bPre0 = *(const float4*)&W[(size_t)(k0 + br0) * N + colBase + bc0];
            bPre1 = *(const float4*)&W[(size_t)(k0 + br1) * N + colBase + bc1];
        }

        #pragma unroll
        for (int ks = 0; ks < 2; ks++) {
            int kb = ks * 8;
            unsigned af[2][4];
            #pragma unroll
            for (int mi = 0; mi < 2; mi++) {
                const float* ap = &As[cur][(wm + mi * 16 + gid) * ASTR + kb + tig];
                af[mi][0] = f2tf(ap[0]);
                af[mi][1] = f2tf(ap[8 * ASTR]);
                af[mi][2] = f2tf(ap[4]);
                af[mi][3] = f2tf(ap[8 * ASTR + 4]);
            }
            unsigned bf[8][2];
            #pragma unroll
            for (int ni = 0; ni < 8; ni++) {
                const float* bp = &Bs[cur][(kb + tig) * BSTR + wn + ni * 8 + gid];
                bf[ni][0] = f2tf(bp[0]);
                bf[ni][1] = f2tf(bp[4 * BSTR]);
            }
            #pragma unroll
            for (int mi = 0; mi < 2; mi++)
                #pragma unroll
                for (int ni = 0; ni < 8; ni++)
                    mma_tf32(c[mi][ni], af[mi], bf[ni]);
        }

        if (hasNext) {
            int nb = cur ^ 1;
            *(float4*)&As[nb][ar0 * ASTR + ac0] = aPre0;
            *(float4*)&As[nb][ar1 * ASTR + ac1] = aPre1;
            *(float4*)&Bs[nb][br0 * BSTR + bc0] = bPre0;
            *(float4*)&Bs[nb][br1 * BSTR + bc1] = bPre1;
            __syncthreads();
        }
    }

    // epilogue
    #pragma unroll
    for (int mi = 0; mi < 2; mi++) {
        size_t r0 = rowBase + wm + mi * 16 + gid;
        size_t r1 = r0 + 8;
        #pragma unroll
        for (int ni = 0; ni < 8; ni++) {
            size_t col = colBase + wn + ni * 8 + tig * 2;
            float b0 = bias[col], b1 = bias[col + 1];
            float v0 = (c[mi][ni][0] + b0) * scale;
            float v1 = (c[mi][ni][1] + b1) * scale;
            float v2 = (c[mi][ni][2] + b0) * scale;
            float v3 = (c[mi][ni][3] + b1) * scale;
            if (act == 1) {
                v0 = 0.5f * v0 * (1.0f + erff(v0 * 0.70710678f));
                v1 = 0.5f * v1 * (1.0f + erff(v1 * 0.70710678f));
                v2 = 0.5f * v2 * (1.0f + erff(v2 * 0.70710678f));
                v3 = 0.5f * v3 * (1.0f + erff(v3 * 0.70710678f));
            }
            *(float2*)&Co[r0 * N + col] = make_float2(v0, v1);
            *(float2*)&Co[r1 * N + col] = make_float2(v2, v3);
        }
    }
}

// ---------------- tiled sliding-window attention ----------------
// grid = (S_/32, H_, B_), 256 threads, dynamic smem.
// smem (floats): qT[64][36] | kv[64*68] | sc[32][776] | inv[32] | mvalid[64]
#define QT_OFF 0
#define KV_OFF 2304
#define SC_OFF 6656
#define SCW    776
#define INV_OFF 31488
#define MV_OFF  31520
#define SWA_SMEM ((31584) * 4)

__global__ __launch_bounds__(256) void sw_attn_kernel(
        const float* __restrict__ q,
        const float* __restrict__ k,
        const float* __restrict__ v,
        const int* __restrict__ mask,
        float* __restrict__ ctx) {
    extern __shared__ float sm[];
    float* qT  = sm + QT_OFF;
    float* kv  = sm + KV_OFF;
    float* sc  = sm + SC_OFF;
    float* inv = sm + INV_OFF;
    float* mv  = sm + MV_OFF;

    int tid = threadIdx.x;
    int h = blockIdx.y, b = blockIdx.z;
    int qbase = blockIdx.x * 32;
    int n = qbase / C_;
    int cbase = qbase % C_;
    int j0 = (n - 1) * C_;

    // load q transposed: qT[d][qi]
    {
        #pragma unroll
        for (int p = 0; p < 2; p++) {
            int s = tid + p * 256;
            int r = s >> 4, c4 = (s & 15) * 4;
            float4 qv = *(const float4*)&q[((size_t)(b * S_ + qbase + r)) * D_ + h * DH_ + c4];
            qT[(c4 + 0) * 36 + r] = qv.x;
            qT[(c4 + 1) * 36 + r] = qv.y;
            qT[(c4 + 2) * 36 + r] = qv.z;
            qT[(c4 + 3) * 36 + r] = qv.w;
        }
    }

    int qgrp = tid >> 4;          // 0..15 -> q rows {2qgrp, 2qgrp+1}
    int kgrp = tid & 15;          // 0..15 -> keys {4kgrp..4kgrp+3}
    int c0 = cbase + 2 * qgrp;    // band base for row qi0
    int c1 = c0 + 1;

    // ---- score phase ----
    for (int kt = 0; kt < 12; kt++) {
        __syncthreads();
        // load k tile transposed into kv: kv[d*68 + r]
        #pragma unroll
        for (int p = 0; p < 4; p++) {
            int s = tid + p * 256;
            int r = s >> 4, c4 = (s & 15) * 4;
            int j = j0 + kt * 64 + r;
            float4 kvv = make_float4(0.f, 0.f, 0.f, 0.f);
            bool inr = (j >= 0) && (j < S_);
            if (inr)
                kvv = *(const float4*)&k[((size_t)(b * S_ + j)) * D_ + h * DH_ + c4];
            kv[(c4 + 0) * 68 + r] = kvv.x;
            kv[(c4 + 1) * 68 + r] = kvv.y;
            kv[(c4 + 2) * 68 + r] = kvv.z;
            kv[(c4 + 3) * 68 + r] = kvv.w;
            if (c4 == 0)
                mv[r] = (j > 0 && j < S_ && mask[b * S_ + j] > 0) ? 1.0f : 0.0f;
        }
        __syncthreads();

        float acc0[4] = {0.f, 0.f, 0.f, 0.f};
        float acc1[4] = {0.f, 0.f, 0.f, 0.f};
        #pragma unroll 4
        for (int d = 0; d < 64; d++) {
            float4 kvv = *(float4*)&kv[d * 68 + 4 * kgrp];
            float q0 = qT[d * 36 + 2 * qgrp];
            float q1 = qT[d * 36 + 2 * qgrp + 1];
            acc0[0] = fmaf(q0, kvv.x, acc0[0]);
            acc0[1] = fmaf(q0, kvv.y, acc0[1]);
            acc0[2] = fmaf(q0, kvv.z, acc0[2]);
            acc0[3] = fmaf(q0, kvv.w, acc0[3]);
            acc1[0] = fmaf(q1, kvv.x, acc1[0]);
            acc1[1] = fmaf(q1, kvv.y, acc1[1]);
            acc1[2] = fmaf(q1, kvv.z, acc1[2]);
            acc1[3] = fmaf(q1, kvv.w, acc1[3]);
        }
        #pragma unroll
        for (int u = 0; u < 4; u++) {
            int kkl = 4 * kgrp + u;
            int kk = kt * 64 + kkl;
            float valid = mv[kkl];
            bool b0 = (kk >= c0) && (kk <= c0 + 2 * C_) && (valid > 0.5f);
            bool b1 = (kk >= c1) && (kk <= c1 + 2 * C_) && (valid > 0.5f);
            sc[(2 * qgrp)     * SCW + kk] = b0 ? acc0[u] : NEGV;
            sc[(2 * qgrp + 1) * SCW + kk] = b1 ? acc1[u] : NEGV;
        }
    }

    // global-token score column (768)
    if (tid < 32) {
        int qi = tid;
        float acc = 0.0f;
        const float* k0p = k + ((size_t)(b * S_)) * D_ + h * DH_;
        for (int d = 0; d < 64; d++)
            acc = fmaf(qT[d * 36 + qi], k0p[d], acc);
        bool gm = mask[b * S_] > 0;
        sc[qi * SCW + 3 * C_] = gm ? acc : NEGV;
    }
    __syncthreads();

    // ---- softmax: warp w handles rows w, w+8, w+16, w+24 ----
    {
        int lane = tid & 31, w = tid >> 5;
        for (int rr = 0; rr < 4; rr++) {
            int qi = w + rr * 8;
            float* row = sc + qi * SCW;
            float m = -INFINITY;
            for (int j = lane; j < 3 * C_ + 1; j += 32) m = fmaxf(m, row[j]);
            m = warp_max(m);
            float s = 0.0f;
            for (int j = lane; j < 3 * C_ + 1; j += 32) {
                float e = __expf(row[j] - m);
                row[j] = e;
                s += e;
            }
            s = warp_sum(s);
            if (lane == 0) inv[qi] = 1.0f / s;
        }
    }

    // ---- v phase ----
    int dgrp = tid & 15;          // 4 d's
    float vacc0[4] = {0.f, 0.f, 0.f, 0.f};
    float vacc1[4] = {0.f, 0.f, 0.f, 0.f};
    for (int kt = 0; kt < 12; kt++) {
        __syncthreads();
        #pragma unroll
        for (int p = 0; p < 4; p++) {
            int s = tid + p * 256;
            int r = s >> 4, c4 = (s & 15) * 4;
            int j = j0 + kt * 64 + r;
            float4 vv = make_float4(0.f, 0.f, 0.f, 0.f);
            if (j >= 0 && j < S_)
                vv = *(const float4*)&v[((size_t)(b * S_ + j)) * D_ + h * DH_ + c4];
            *(float4*)&kv[r * 68 + c4] = vv;
        }
        __syncthreads();

        #pragma unroll 4
        for (int kk = 0; kk < 64; kk++) {
            int kkg = kt * 64 + kk;
            float p0 = sc[(2 * qgrp)     * SCW + kkg];
            float p1 = sc[(2 * qgrp + 1) * SCW + kkg];
            float4 vv = *(float4*)&kv[kk * 68 + 4 * dgrp];
            vacc0[0] = fmaf(p0, vv.x, vacc0[0]);
            vacc0[1] = fmaf(p0, vv.y, vacc0[1]);
            vacc0[2] = fmaf(p0, vv.z, vacc0[2]);
            vacc0[3] = fmaf(p0, vv.w, vacc0[3]);
            vacc1[0] = fmaf(p1, vv.x, vacc1[0]);
            vacc1[1] = fmaf(p1, vv.y, vacc1[1]);
            vacc1[2] = fmaf(p1, vv.z, vacc1[2]);
            vacc1[3] = fmaf(p1, vv.w, vacc1[3]);
        }
    }

    // add global-token contribution and write out
    {
        int qi0 = 2 * qgrp, qi1 = qi0 + 1;
        float g0 = sc[qi0 * SCW + 3 * C_];
        float g1 = sc[qi1 * SCW + 3 * C_];
        float i0 = inv[qi0], i1 = inv[qi1];
        const float* v0p = v + ((size_t)(b * S_)) * D_ + h * DH_ + 4 * dgrp;
        float4 gv = *(const float4*)v0p;
        float4 o0, o1;
        o0.x = (vacc0[0] + g0 * gv.x) * i0;
        o0.y = (vacc0[1] + g0 * gv.y) * i0;
        o0.z = (vacc0[2] + g0 * gv.z) * i0;
        o0.w = (vacc0[3] + g0 * gv.w) * i0;
        o1.x = (vacc1[0] + g1 * gv.x) * i1;
        o1.y = (vacc1[1] + g1 * gv.y) * i1;
        o1.z = (vacc1[2] + g1 * gv.z) * i1;
        o1.w = (vacc1[3] + g1 * gv.w) * i1;
        *(float4*)&ctx[((size_t)(b * S_ + qbase + qi0)) * D_ + h * DH_ + 4 * dgrp] = o0;
        *(float4*)&ctx[((size_t)(b * S_ + qbase + qi1)) * D_ + h * DH_ + 4 * dgrp] = o1;
    }
}

// ---------------- full attention for query row 0: one block per (b,h) ----------------
__global__ void global_attn_kernel(const float* __restrict__ q,
                                   const float* __restrict__ k,
                                   const float* __restrict__ v,
                                   const int* __restrict__ mask,
                                   float* __restrict__ ctx) {
    __shared__ float qs[64];
    __shared__ float sc[S_];
    __shared__ float red[32];
    __shared__ float cpart[256];
    int h = blockIdx.x, b = blockIdx.y;
    int tid = threadIdx.x;
    const float* qp = q + ((size_t)(b * S_)) * D_ + h * DH_;
    if (tid < 16) ((float4*)qs)[tid] = ((const float4*)qp)[tid];
    __syncthreads();

    for (int j = tid; j < S_; j += 256) {
        float s = NEGV;
        if (mask[b * S_ + j] > 0) {
            const float4* kp = (const float4*)(k + ((size_t)(b * S_ + j)) * D_ + h * DH_);
            float acc = 0.0f;
            #pragma unroll
            for (int d4 = 0; d4 < 16; d4++) {
                float4 kvv = kp[d4];
                float4 qv = ((const float4*)qs)[d4];
                acc += kvv.x * qv.x + kvv.y * qv.y + kvv.z * qv.z + kvv.w * qv.w;
            }
            s = acc;
        }
        sc[j] = s;
    }
    __syncthreads();

    float m = -INFINITY;
    for (int j = tid; j < S_; j += 256) m = fmaxf(m, sc[j]);
    m = block_max(m, red);
    float lsum = 0.0f;
    for (int j = tid; j < S_; j += 256) {
        float e = __expf(sc[j] - m);
        sc[j] = e;
        lsum += e;
    }
    float sum = block_sum(lsum, red);
    float inv = 1.0f / sum;

    int d = tid & 63, part = tid >> 6;
    float accum = 0.0f;
    for (int j = part; j < S_; j += 4)
        accum += sc[j] * v[((size_t)(b * S_ + j)) * D_ + h * DH_ + d];
    cpart[tid] = accum;
    __syncthreads();
    if (part == 0)
        ctx[((size_t)(b * S_)) * D_ + h * DH_ + d] =
            (cpart[d] + cpart[64 + d] + cpart[128 + d] + cpart[192 + d]) * inv;
}

// ---------------- classifier head ----------------
__global__ void cls_kernel(const float* __restrict__ h,
                           const float* __restrict__ W,
                           const float* __restrict__ bias,
                           float* __restrict__ out) {
    int w = threadIdx.x >> 5, lane = threadIdx.x & 31;
    if (w < B_ * 3) {
        int b = w / 3, c = w % 3;
        float acc = 0.0f;
        for (int kx = lane; kx < D_; kx += 32)
            acc += h[((size_t)(b * S_)) * D_ + kx] * W[kx * 3 + c];
        acc = warp_sum(acc);
        if (lane == 0) out[b * 3 + c] = acc + bias[c];
    }
}

// ---------------- launch ----------------
extern "C" void kernel_launch(void* const* d_in, const int* in_sizes, int n_in,
                              void* d_out, int out_size) {
    const int*   ids      = (const int*)d_in[0];
    const int*   mask     = (const int*)d_in[1];
    const float* emb_tok  = (const float*)d_in[2];
    const float* emb_pos  = (const float*)d_in[3];
    const float* emb_ln_g = (const float*)d_in[4];
    const float* emb_ln_b = (const float*)d_in[5];
    const float* Wq = (const float*)d_in[6];
    const float* bq = (const float*)d_in[7];
    const float* Wk = (const float*)d_in[8];
    const float* bk = (const float*)d_in[9];
    const float* Wv = (const float*)d_in[10];
    const float* bv = (const float*)d_in[11];
    const float* Wo = (const float*)d_in[12];
    const float* bo = (const float*)d_in[13];
    const float* ln1_g = (const float*)d_in[14];
    const float* ln1_b = (const float*)d_in[15];
    const float* W1 = (const float*)d_in[16];
    const float* b1 = (const float*)d_in[17];
    const float* W2 = (const float*)d_in[18];
    const float* b2 = (const float*)d_in[19];
    const float* ln2_g = (const float*)d_in[20];
    const float* ln2_b = (const float*)d_in[21];
    const float* clsW = (const float*)d_in[22];
    const float* clsb = (const float*)d_in[23];

    float *h, *q, *k, *v, *ctx, *t, *f;
    cudaGetSymbolAddress((void**)&h,   g_h);
    cudaGetSymbolAddress((void**)&q,   g_q);
    cudaGetSymbolAddress((void**)&k,   g_k);
    cudaGetSymbolAddress((void**)&v,   g_v);
    cudaGetSymbolAddress((void**)&ctx, g_ctx);
    cudaGetSymbolAddress((void**)&t,   g_t);
    cudaGetSymbolAddress((void**)&f,   g_f);

    static int attr_done = 0;
    if (!attr_done) {
        cudaFuncSetAttribute(sw_attn_kernel,
                             cudaFuncAttributeMaxDynamicSharedMemorySize, SWA_SMEM);
        attr_done = 1;
    }

    embed_ln_kernel<<<M_, 256>>>(ids, emb_tok, emb_pos, emb_ln_g, emb_ln_b, h);

    for (int l = 0; l < L_; l++) {
        const float* Wql = Wq + (size_t)l * D_ * D_;
        const float* Wkl = Wk + (size_t)l * D_ * D_;
        const float* Wvl = Wv + (size_t)l * D_ * D_;
        const float* Wol = Wo + (size_t)l * D_ * D_;
        const float* W1l = W1 + (size_t)l * D_ * F_;
        const float* W2l = W2 + (size_t)l * F_ * D_;

        dim3 gD(D_ / TBN, M_ / TBM);
        dim3 gF(F_ / TBN, M_ / TBM);

        gemm_tf32_kernel<<<gD, 256>>>(h, Wql, bq + l * D_, q, M_, D_, D_, 0, 0.125f);
        gemm_tf32_kernel<<<gD, 256>>>(h, Wkl, bk + l * D_, k, M_, D_, D_, 0, 1.0f);
        gemm_tf32_kernel<<<gD, 256>>>(h, Wvl, bv + l * D_, v, M_, D_, D_, 0, 1.0f);

        sw_attn_kernel<<<dim3(S_ / 32, H_, B_), 256, SWA_SMEM>>>(q, k, v, mask, ctx);
        global_attn_kernel<<<dim3(H_, B_), 256>>>(q, k, v, mask, ctx);

        gemm_tf32_kernel<<<gD, 256>>>(ctx, Wol, bo + l * D_, t, M_, D_, D_, 0, 1.0f);
        add_ln_kernel<<<M_, 256>>>(h, t, ln1_g + l * D_, ln1_b + l * D_, h);

        gemm_tf32_kernel<<<gF, 256>>>(h, W1l, b1 + l * F_, f, M_, F_, D_, 1, 1.0f);
        gemm_tf32_kernel<<<gD, 256>>>(f, W2l, b2 + l * D_, t, M_, D_, F_, 0, 1.0f);
        add_ln_kernel<<<M_, 256>>>(h, t, ln2_g + l * D_, ln2_b + l * D_, h);
    }

    cls_kernel<<<1, 256>>>(h, clsW, clsb, (float*)d_out);
}

// round 3
// speedup vs baseline: 3.3202x; 1.2082x over previous
#include <cuda_runtime.h>
#include <math.h>

// ---------------- problem constants ----------------
#define B_  2
#define S_  4096
#define D_  768
#define H_  12
#define DH_ 64
#define L_  2
#define F_  3072
#define C_  256
#define M_  (B_*S_)
#define NEGV (-1000000000.0f)

// ---------------- scratch ----------------
__device__ float g_h  [M_ * D_];
__device__ float g_q  [M_ * D_];
__device__ float g_k  [M_ * D_];
__device__ float g_v  [M_ * D_];
__device__ float g_ctx[M_ * D_];
__device__ float g_t  [M_ * D_];
__device__ float g_f  [M_ * F_];

// ---------------- helpers ----------------
__device__ __forceinline__ float warp_sum(float v) {
    #pragma unroll
    for (int o = 16; o; o >>= 1) v += __shfl_xor_sync(0xffffffffu, v, o);
    return v;
}
__device__ __forceinline__ float warp_max(float v) {
    #pragma unroll
    for (int o = 16; o; o >>= 1) v = fmaxf(v, __shfl_xor_sync(0xffffffffu, v, o));
    return v;
}
__device__ float block_sum(float v, float* red) {
    int lane = threadIdx.x & 31, w = threadIdx.x >> 5;
    v = warp_sum(v);
    __syncthreads();
    if (lane == 0) red[w] = v;
    __syncthreads();
    int nw = (blockDim.x + 31) >> 5;
    float r = (threadIdx.x < nw) ? red[threadIdx.x] : 0.0f;
    if (w == 0) { r = warp_sum(r); if (lane == 0) red[0] = r; }
    __syncthreads();
    return red[0];
}
__device__ float block_max(float v, float* red) {
    int lane = threadIdx.x & 31, w = threadIdx.x >> 5;
    v = warp_max(v);
    __syncthreads();
    if (lane == 0) red[w] = v;
    __syncthreads();
    int nw = (blockDim.x + 31) >> 5;
    float r = (threadIdx.x < nw) ? red[threadIdx.x] : -INFINITY;
    if (w == 0) { r = warp_max(r); if (lane == 0) red[0] = r; }
    __syncthreads();
    return red[0];
}

__device__ __forceinline__ unsigned f2tf(float v) {
    unsigned r; asm("cvt.rna.tf32.f32 %0, %1;" : "=r"(r) : "f"(v)); return r;
}
__device__ __forceinline__ void mma_tf32(float* c, const unsigned* a, const unsigned* b) {
    asm volatile(
        "mma.sync.aligned.m16n8k8.row.col.f32.tf32.tf32.f32 "
        "{%0,%1,%2,%3},{%4,%5,%6,%7},{%8,%9},{%0,%1,%2,%3};\n"
        : "+f"(c[0]), "+f"(c[1]), "+f"(c[2]), "+f"(c[3])
        : "r"(a[0]), "r"(a[1]), "r"(a[2]), "r"(a[3]), "r"(b[0]), "r"(b[1]));
}

// ---------------- embedding + layernorm ----------------
__global__ void embed_ln_kernel(const int* __restrict__ ids,
                                const float* __restrict__ tok,
                                const float* __restrict__ pos,
                                const float* __restrict__ g,
                                const float* __restrict__ be,
                                float* __restrict__ out) {
    __shared__ float red[32];
    int row = blockIdx.x;
    int s = row % S_;
    int id = ids[row];
    const float* tp = tok + (size_t)id * D_;
    const float* pp = pos + (size_t)s  * D_;
    float vals[3]; float lsum = 0.0f;
    #pragma unroll
    for (int i = 0; i < 3; i++) {
        int c = threadIdx.x + i * 256;
        vals[i] = tp[c] + pp[c];
        lsum += vals[i];
    }
    float mean = block_sum(lsum, red) * (1.0f / D_);
    float lv = 0.0f;
    #pragma unroll
    for (int i = 0; i < 3; i++) { float d = vals[i] - mean; lv += d * d; }
    float var = block_sum(lv, red) * (1.0f / D_);
    float inv = rsqrtf(var + 1e-5f);
    float* op = out + (size_t)row * D_;
    #pragma unroll
    for (int i = 0; i < 3; i++) {
        int c = threadIdx.x + i * 256;
        op[c] = (vals[i] - mean) * inv * g[c] + be[c];
    }
}

// ---------------- residual add + layernorm ----------------
__global__ void add_ln_kernel(const float* __restrict__ x,
                              const float* __restrict__ r,
                              const float* __restrict__ g,
                              const float* __restrict__ be,
                              float* __restrict__ out) {
    __shared__ float red[32];
    int row = blockIdx.x;
    const float* xp = x + (size_t)row * D_;
    const float* rp = r + (size_t)row * D_;
    float vals[3]; float lsum = 0.0f;
    #pragma unroll
    for (int i = 0; i < 3; i++) {
        int c = threadIdx.x + i * 256;
        vals[i] = xp[c] + rp[c];
        lsum += vals[i];
    }
    float mean = block_sum(lsum, red) * (1.0f / D_);
    float lv = 0.0f;
    #pragma unroll
    for (int i = 0; i < 3; i++) { float d = vals[i] - mean; lv += d * d; }
    float var = block_sum(lv, red) * (1.0f / D_);
    float inv = rsqrtf(var + 1e-5f);
    float* op = out + (size_t)row * D_;
    #pragma unroll
    for (int i = 0; i < 3; i++) {
        int c = threadIdx.x + i * 256;
        op[c] = (vals[i] - mean) * inv * g[c] + be[c];
    }
}

// ---------------- tf32 mma GEMM (cvt at smem store) ----------------
#define TBM 128
#define TBN 128
#define TBK 16
#define ASTR 20
#define BSTR 132

__global__ __launch_bounds__(256) void gemm_tf32_kernel(
        const float* __restrict__ A, const float* __restrict__ W,
        const float* __restrict__ bias, float* __restrict__ Co,
        int M, int N, int K, int act, float scale) {
    __shared__ unsigned As[2][TBM * ASTR];
    __shared__ unsigned Bs[2][TBK * BSTR];

    int tid = threadIdx.x;
    int lane = tid & 31, wid = tid >> 5;
    int wm = (wid & 3) * 32;
    int wn = (wid >> 2) * 64;
    int gid = lane >> 2, tig = lane & 3;
    size_t rowBase = (size_t)blockIdx.y * TBM;
    size_t colBase = (size_t)blockIdx.x * TBN;

    int s0 = tid, s1 = tid + 256;
    int ar0 = s0 >> 2, ac0 = (s0 & 3) * 4;
    int ar1 = s1 >> 2, ac1 = (s1 & 3) * 4;
    int br0 = s0 >> 5, bc0 = (s0 & 31) * 4;
    int br1 = s1 >> 5, bc1 = (s1 & 31) * 4;

    float c[2][8][4];
    #pragma unroll
    for (int mi = 0; mi < 2; mi++)
        #pragma unroll
        for (int ni = 0; ni < 8; ni++)
            #pragma unroll
            for (int q = 0; q < 4; q++) c[mi][ni][q] = 0.0f;

    int ntiles = K / TBK;

    float4 aPre0, aPre1, bPre0, bPre1;
    aPre0 = *(const float4*)&A[(rowBase + ar0) * K + ac0];
    aPre1 = *(const float4*)&A[(rowBase + ar1) * K + ac1];
    bPre0 = *(const float4*)&W[(size_t)br0 * N + colBase + bc0];
    bPre1 = *(const float4*)&W[(size_t)br1 * N + colBase + bc1];
    {
        unsigned* p;
        p = &As[0][ar0 * ASTR + ac0];
        p[0]=f2tf(aPre0.x); p[1]=f2tf(aPre0.y); p[2]=f2tf(aPre0.z); p[3]=f2tf(aPre0.w);
        p = &As[0][ar1 * ASTR + ac1];
        p[0]=f2tf(aPre1.x); p[1]=f2tf(aPre1.y); p[2]=f2tf(aPre1.z); p[3]=f2tf(aPre1.w);
        p = &Bs[0][br0 * BSTR + bc0];
        p[0]=f2tf(bPre0.x); p[1]=f2tf(bPre0.y); p[2]=f2tf(bPre0.z); p[3]=f2tf(bPre0.w);
        p = &Bs[0][br1 * BSTR + bc1];
        p[0]=f2tf(bPre1.x); p[1]=f2tf(bPre1.y); p[2]=f2tf(bPre1.z); p[3]=f2tf(bPre1.w);
    }
    __syncthreads();

    for (int kt = 0; kt < ntiles; kt++) {
        int cur = kt & 1;
        bool hasNext = (kt + 1) < ntiles;
        if (hasNext) {
            int k0 = (kt + 1) * TBK;
            aPre0 = *(const float4*)&A[(rowBase + ar0) * K + k0 + ac0];
            aPre1 = *(const float4*)&A[(rowBase + ar1) * K + k0 + ac1];
            bPre0 = *(const float4*)&W[(size_t)(k0 + br0) * N + colBase + bc0];
            bPre1 = *(const float4*)&W[(size_t)(k0 + br1) * N + colBase + bc1];
        }

        #pragma unroll
        for (int ks = 0; ks < 2; ks++) {
            int kb = ks * 8;
            unsigned af[2][4];
            #pragma unroll
            for (int mi = 0; mi < 2; mi++) {
                const unsigned* ap = &As[cur][(wm + mi * 16 + gid) * ASTR + kb + tig];
                af[mi][0] = ap[0];
                af[mi][1] = ap[8 * ASTR];
                af[mi][2] = ap[4];
                af[mi][3] = ap[8 * ASTR + 4];
            }
            unsigned bf[8][2];
            #pragma unroll
            for (int ni = 0; ni < 8; ni++) {
                const unsigned* bp = &Bs[cur][(kb + tig) * BSTR + wn + ni * 8 + gid];
                bf[ni][0] = bp[0];
                bf[ni][1] = bp[4 * BSTR];
            }
            #pragma unroll
            for (int mi = 0; mi < 2; mi++)
                #pragma unroll
                for (int ni = 0; ni < 8; ni++)
                    mma_tf32(c[mi][ni], af[mi], bf[ni]);
        }

        if (hasNext) {
            int nb = cur ^ 1;
            unsigned* p;
            p = &As[nb][ar0 * ASTR + ac0];
            p[0]=f2tf(aPre0.x); p[1]=f2tf(aPre0.y); p[2]=f2tf(aPre0.z); p[3]=f2tf(aPre0.w);
            p = &As[nb][ar1 * ASTR + ac1];
            p[0]=f2tf(aPre1.x); p[1]=f2tf(aPre1.y); p[2]=f2tf(aPre1.z); p[3]=f2tf(aPre1.w);
            p = &Bs[nb][br0 * BSTR + bc0];
            p[0]=f2tf(bPre0.x); p[1]=f2tf(bPre0.y); p[2]=f2tf(bPre0.z); p[3]=f2tf(bPre0.w);
            p = &Bs[nb][br1 * BSTR + bc1];
            p[0]=f2tf(bPre1.x); p[1]=f2tf(bPre1.y); p[2]=f2tf(bPre1.z); p[3]=f2tf(bPre1.w);
            __syncthreads();
        }
    }

    #pragma unroll
    for (int mi = 0; mi < 2; mi++) {
        size_t r0 = rowBase + wm + mi * 16 + gid;
        size_t r1 = r0 + 8;
        #pragma unroll
        for (int ni = 0; ni < 8; ni++) {
            size_t col = colBase + wn + ni * 8 + tig * 2;
            float b0 = bias[col], b1 = bias[col + 1];
            float v0 = (c[mi][ni][0] + b0) * scale;
            float v1 = (c[mi][ni][1] + b1) * scale;
            float v2 = (c[mi][ni][2] + b0) * scale;
            float v3 = (c[mi][ni][3] + b1) * scale;
            if (act == 1) {
                v0 = 0.5f * v0 * (1.0f + erff(v0 * 0.70710678f));
                v1 = 0.5f * v1 * (1.0f + erff(v1 * 0.70710678f));
                v2 = 0.5f * v2 * (1.0f + erff(v2 * 0.70710678f));
                v3 = 0.5f * v3 * (1.0f + erff(v3 * 0.70710678f));
            }
            *(float2*)&Co[r0 * N + col] = make_float2(v0, v1);
            *(float2*)&Co[r1 * N + col] = make_float2(v2, v3);
        }
    }
}

// ---------------- sliding-window attention (tensor-core) ----------------
// grid = (S_/32, H_, B_), 256 threads (8 warps)
// smem floats: qU 32x68(uint) | kvU 64x68(uint) | sc 32x772 | inv[32] | mv[64]
#define SCW2 772
#define AT_Q   0
#define AT_KV  2176
#define AT_SC  6528
#define AT_INV 31232
#define AT_MV  31264
#define AT_SMEM ((31328) * 4)

__global__ __launch_bounds__(256) void sw_attn_kernel(
        const float* __restrict__ q,
        const float* __restrict__ k,
        const float* __restrict__ v,
        const int* __restrict__ mask,
        float* __restrict__ ctx) {
    extern __shared__ float sm[];
    unsigned* qU  = (unsigned*)(sm + AT_Q);
    unsigned* kvU = (unsigned*)(sm + AT_KV);
    float* sc  = sm + AT_SC;
    float* inv = sm + AT_INV;
    float* mv  = sm + AT_MV;
    unsigned* scU = (unsigned*)sc;

    int tid = threadIdx.x;
    int lane = tid & 31, w = tid >> 5;
    int gid = lane >> 2, ti = lane & 3;
    int h = blockIdx.y, b = blockIdx.z;
    int qbase = blockIdx.x * 32;
    int n = qbase / C_;
    int cbase = qbase % C_;
    int j0 = (n - 1) * C_;
    int n0 = w * 8;

    // stage q (tf32) [q][d]
    #pragma unroll
    for (int p = 0; p < 2; p++) {
        int s = tid + p * 256;
        int r = s >> 4, c4 = (s & 15) * 4;
        float4 qv = *(const float4*)&q[((size_t)(b * S_ + qbase + r)) * D_ + h * DH_ + c4];
        qU[r * 68 + c4 + 0] = f2tf(qv.x);
        qU[r * 68 + c4 + 1] = f2tf(qv.y);
        qU[r * 68 + c4 + 2] = f2tf(qv.z);
        qU[r * 68 + c4 + 3] = f2tf(qv.w);
    }
    __syncthreads();

    // hoist Q fragments: aF[mi][ks][4]
    unsigned aF[2][8][4];
    #pragma unroll
    for (int mi = 0; mi < 2; mi++)
        #pragma unroll
        for (int ks = 0; ks < 8; ks++) {
            const unsigned* ap = &qU[(mi * 16 + gid) * 68 + ks * 8 + ti];
            aF[mi][ks][0] = ap[0];
            aF[mi][ks][1] = ap[8 * 68];
            aF[mi][ks][2] = ap[4];
            aF[mi][ks][3] = ap[8 * 68 + 4];
        }

    // ---- score phase: S = Q K^T via mma ----
    for (int kt = 0; kt < 12; kt++) {
        __syncthreads();
        #pragma unroll
        for (int p = 0; p < 4; p++) {
            int s = tid + p * 256;
            int r = s >> 4, c4 = (s & 15) * 4;
            int j = j0 + kt * 64 + r;
            float4 kvv = make_float4(0.f, 0.f, 0.f, 0.f);
            if (j >= 0 && j < S_)
                kvv = *(const float4*)&k[((size_t)(b * S_ + j)) * D_ + h * DH_ + c4];
            unsigned* kp = &kvU[r * 68 + c4];
            kp[0] = f2tf(kvv.x); kp[1] = f2tf(kvv.y);
            kp[2] = f2tf(kvv.z); kp[3] = f2tf(kvv.w);
            if (c4 == 0)
                mv[r] = (j > 0 && j < S_ && mask[b * S_ + j] > 0) ? 1.0f : 0.0f;
        }
        __syncthreads();

        float cS[2][4];
        #pragma unroll
        for (int mi = 0; mi < 2; mi++)
            #pragma unroll
            for (int qq = 0; qq < 4; qq++) cS[mi][qq] = 0.0f;

        #pragma unroll
        for (int ks = 0; ks < 8; ks++) {
            unsigned bb[2];
            bb[0] = kvU[(n0 + gid) * 68 + ks * 8 + ti];
            bb[1] = kvU[(n0 + gid) * 68 + ks * 8 + ti + 4];
            mma_tf32(cS[0], aF[0][ks], bb);
            mma_tf32(cS[1], aF[1][ks], bb);
        }

        int kk0 = kt * 64 + n0 + 2 * ti;
        float valid0 = mv[n0 + 2 * ti], valid1 = mv[n0 + 2 * ti + 1];
        #pragma unroll
        for (int mi = 0; mi < 2; mi++) {
            int r0 = mi * 16 + gid, r1 = r0 + 8;
            int cq0 = cbase + r0, cq1 = cbase + r1;
            bool ok00 = (valid0 > 0.5f) && (kk0 >= cq0) && (kk0 <= cq0 + 2 * C_);
            bool ok01 = (valid1 > 0.5f) && (kk0 + 1 >= cq0) && (kk0 + 1 <= cq0 + 2 * C_);
            bool ok10 = (valid0 > 0.5f) && (kk0 >= cq1) && (kk0 <= cq1 + 2 * C_);
            bool ok11 = (valid1 > 0.5f) && (kk0 + 1 >= cq1) && (kk0 + 1 <= cq1 + 2 * C_);
            sc[r0 * SCW2 + kk0]     = ok00 ? cS[mi][0] : NEGV;
            sc[r0 * SCW2 + kk0 + 1] = ok01 ? cS[mi][1] : NEGV;
            sc[r1 * SCW2 + kk0]     = ok10 ? cS[mi][2] : NEGV;
            sc[r1 * SCW2 + kk0 + 1] = ok11 ? cS[mi][3] : NEGV;
        }
    }

    // global-token score
    if (tid < 32) {
        float acc = 0.0f;
        const float* k0p = k + ((size_t)(b * S_)) * D_ + h * DH_;
        #pragma unroll 8
        for (int d = 0; d < 64; d++)
            acc = fmaf(__uint_as_float(qU[tid * 68 + d]), k0p[d], acc);
        sc[tid * SCW2 + 3 * C_] = (mask[b * S_] > 0) ? acc : NEGV;
    }
    __syncthreads();

    // ---- softmax (store probs tf32-rounded for mma A use) ----
    for (int rr = 0; rr < 4; rr++) {
        int qi = w + rr * 8;
        float* row = sc + qi * SCW2;
        float m = -INFINITY;
        for (int j = lane; j < 3 * C_ + 1; j += 32) m = fmaxf(m, row[j]);
        m = warp_max(m);
        float ssum = 0.0f;
        for (int j = lane; j < 3 * C_ + 1; j += 32) {
            float e = __expf(row[j] - m);
            ssum += e;
            row[j] = __uint_as_float(f2tf(e));
        }
        ssum = warp_sum(ssum);
        if (lane == 0) inv[qi] = 1.0f / ssum;
    }

    // ---- PV phase: O = P V via mma (V staged transposed w/ xor swizzle) ----
    float cO[2][4];
    #pragma unroll
    for (int mi = 0; mi < 2; mi++)
        #pragma unroll
        for (int qq = 0; qq < 4; qq++) cO[mi][qq] = 0.0f;

    for (int kt = 0; kt < 12; kt++) {
        __syncthreads();
        #pragma unroll
        for (int p = 0; p < 4; p++) {
            int s = tid + p * 256;
            int r = s >> 4, c4 = (s & 15) * 4;   // r = local key, c4 = d base
            int j = j0 + kt * 64 + r;
            float4 vv = make_float4(0.f, 0.f, 0.f, 0.f);
            if (j >= 0 && j < S_)
                vv = *(const float4*)&v[((size_t)(b * S_ + j)) * D_ + h * DH_ + c4];
            // vT[d][key] with key ^ (d>>3) swizzle
            kvU[(c4 + 0) * 68 + (r ^ ((c4 + 0) >> 3))] = f2tf(vv.x);
            kvU[(c4 + 1) * 68 + (r ^ ((c4 + 1) >> 3))] = f2tf(vv.y);
            kvU[(c4 + 2) * 68 + (r ^ ((c4 + 2) >> 3))] = f2tf(vv.z);
            kvU[(c4 + 3) * 68 + (r ^ ((c4 + 3) >> 3))] = f2tf(vv.w);
        }
        __syncthreads();

        #pragma unroll
        for (int ks = 0; ks < 8; ks++) {
            unsigned bb[2];
            int drow = n0 + gid;              // drow>>3 == w
            bb[0] = kvU[drow * 68 + ((ks * 8 + ti) ^ w)];
            bb[1] = kvU[drow * 68 + ((ks * 8 + ti + 4) ^ w)];
            #pragma unroll
            for (int mi = 0; mi < 2; mi++) {
                unsigned aa[4];
                const unsigned* pp = &scU[(mi * 16 + gid) * SCW2 + kt * 64 + ks * 8 + ti];
                aa[0] = pp[0];
                aa[1] = pp[8 * SCW2];
                aa[2] = pp[4];
                aa[3] = pp[8 * SCW2 + 4];
                mma_tf32(cO[mi], aa, bb);
            }
        }
    }

    // add global-token contribution and write
    {
        const float* v0p = v + ((size_t)(b * S_)) * D_ + h * DH_;
        int d0 = n0 + 2 * ti;
        float gv0 = v0p[d0], gv1 = v0p[d0 + 1];
        #pragma unroll
        for (int mi = 0; mi < 2; mi++) {
            int r0 = mi * 16 + gid, r1 = r0 + 8;
            float g0 = sc[r0 * SCW2 + 3 * C_], g1 = sc[r1 * SCW2 + 3 * C_];
            float i0 = inv[r0], i1 = inv[r1];
            float2 o0 = make_float2((cO[mi][0] + g0 * gv0) * i0,
                                    (cO[mi][1] + g0 * gv1) * i0);
            float2 o1 = make_float2((cO[mi][2] + g1 * gv0) * i1,
                                    (cO[mi][3] + g1 * gv1) * i1);
            *(float2*)&ctx[((size_t)(b * S_ + qbase + r0)) * D_ + h * DH_ + d0] = o0;
            *(float2*)&ctx[((size_t)(b * S_ + qbase + r1)) * D_ + h * DH_ + d0] = o1;
        }
    }
}

// ---------------- full attention for query row 0 ----------------
__global__ void global_attn_kernel(const float* __restrict__ q,
                                   const float* __restrict__ k,
                                   const float* __restrict__ v,
                                   const int* __restrict__ mask,
                                   float* __restrict__ ctx) {
    __shared__ float qs[64];
    __shared__ float sc[S_];
    __shared__ float red[32];
    __shared__ float cpart[256];
    int h = blockIdx.x, b = blockIdx.y;
    int tid = threadIdx.x;
    const float* qp = q + ((size_t)(b * S_)) * D_ + h * DH_;
    if (tid < 16) ((float4*)qs)[tid] = ((const float4*)qp)[tid];
    __syncthreads();

    for (int j = tid; j < S_; j += 256) {
        float s = NEGV;
        if (mask[b * S_ + j] > 0) {
            const float4* kp = (const float4*)(k + ((size_t)(b * S_ + j)) * D_ + h * DH_);
            float acc = 0.0f;
            #pragma unroll
            for (int d4 = 0; d4 < 16; d4++) {
                float4 kvv = kp[d4];
                float4 qv = ((const float4*)qs)[d4];
                acc += kvv.x * qv.x + kvv.y * qv.y + kvv.z * qv.z + kvv.w * qv.w;
            }
            s = acc;
        }
        sc[j] = s;
    }
    __syncthreads();

    float m = -INFINITY;
    for (int j = tid; j < S_; j += 256) m = fmaxf(m, sc[j]);
    m = block_max(m, red);
    float lsum = 0.0f;
    for (int j = tid; j < S_; j += 256) {
        float e = __expf(sc[j] - m);
        sc[j] = e;
        lsum += e;
    }
    float sum = block_sum(lsum, red);
    float inv = 1.0f / sum;

    int d = tid & 63, part = tid >> 6;
    float accum = 0.0f;
    for (int j = part; j < S_; j += 4)
        accum += sc[j] * v[((size_t)(b * S_ + j)) * D_ + h * DH_ + d];
    cpart[tid] = accum;
    __syncthreads();
    if (part == 0)
        ctx[((size_t)(b * S_)) * D_ + h * DH_ + d] =
            (cpart[d] + cpart[64 + d] + cpart[128 + d] + cpart[192 + d]) * inv;
}

// ---------------- classifier head ----------------
__global__ void cls_kernel(const float* __restrict__ h,
                           const float* __restrict__ W,
                           const float* __restrict__ bias,
                           float* __restrict__ out) {
    int w = threadIdx.x >> 5, lane = threadIdx.x & 31;
    if (w < B_ * 3) {
        int b = w / 3, c = w % 3;
        float acc = 0.0f;
        for (int kx = lane; kx < D_; kx += 32)
            acc += h[((size_t)(b * S_)) * D_ + kx] * W[kx * 3 + c];
        acc = warp_sum(acc);
        if (lane == 0) out[b * 3 + c] = acc + bias[c];
    }
}

// ---------------- launch ----------------
extern "C" void kernel_launch(void* const* d_in, const int* in_sizes, int n_in,
                              void* d_out, int out_size) {
    const int*   ids      = (const int*)d_in[0];
    const int*   mask     = (const int*)d_in[1];
    const float* emb_tok  = (const float*)d_in[2];
    const float* emb_pos  = (const float*)d_in[3];
    const float* emb_ln_g = (const float*)d_in[4];
    const float* emb_ln_b = (const float*)d_in[5];
    const float* Wq = (const float*)d_in[6];
    const float* bq = (const float*)d_in[7];
    const float* Wk = (const float*)d_in[8];
    const float* bk = (const float*)d_in[9];
    const float* Wv = (const float*)d_in[10];
    const float* bv = (const float*)d_in[11];
    const float* Wo = (const float*)d_in[12];
    const float* bo = (const float*)d_in[13];
    const float* ln1_g = (const float*)d_in[14];
    const float* ln1_b = (const float*)d_in[15];
    const float* W1 = (const float*)d_in[16];
    const float* b1 = (const float*)d_in[17];
    const float* W2 = (const float*)d_in[18];
    const float* b2 = (const float*)d_in[19];
    const float* ln2_g = (const float*)d_in[20];
    const float* ln2_b = (const float*)d_in[21];
    const float* clsW = (const float*)d_in[22];
    const float* clsb = (const float*)d_in[23];

    float *h, *q, *k, *v, *ctx, *t, *f;
    cudaGetSymbolAddress((void**)&h,   g_h);
    cudaGetSymbolAddress((void**)&q,   g_q);
    cudaGetSymbolAddress((void**)&k,   g_k);
    cudaGetSymbolAddress((void**)&v,   g_v);
    cudaGetSymbolAddress((void**)&ctx, g_ctx);
    cudaGetSymbolAddress((void**)&t,   g_t);
    cudaGetSymbolAddress((void**)&f,   g_f);

    static int attr_done = 0;
    if (!attr_done) {
        cudaFuncSetAttribute(sw_attn_kernel,
                             cudaFuncAttributeMaxDynamicSharedMemorySize, AT_SMEM);
        attr_done = 1;
    }

    embed_ln_kernel<<<M_, 256>>>(ids, emb_tok, emb_pos, emb_ln_g, emb_ln_b, h);

    for (int l = 0; l < L_; l++) {
        const float* Wql = Wq + (size_t)l * D_ * D_;
        const float* Wkl = Wk + (size_t)l * D_ * D_;
        const float* Wvl = Wv + (size_t)l * D_ * D_;
        const float* Wol = Wo + (size_t)l * D_ * D_;
        const float* W1l = W1 + (size_t)l * D_ * F_;
        const float* W2l = W2 + (size_t)l * F_ * D_;

        dim3 gD(D_ / TBN, M_ / TBM);
        dim3 gF(F_ / TBN, M_ / TBM);

        gemm_tf32_kernel<<<gD, 256>>>(h, Wql, bq + l * D_, q, M_, D_, D_, 0, 0.125f);
        gemm_tf32_kernel<<<gD, 256>>>(h, Wkl, bk + l * D_, k, M_, D_, D_, 0, 1.0f);
        gemm_tf32_kernel<<<gD, 256>>>(h, Wvl, bv + l * D_, v, M_, D_, D_, 0, 1.0f);

        sw_attn_kernel<<<dim3(S_ / 32, H_, B_), 256, AT_SMEM>>>(q, k, v, mask, ctx);
        global_attn_kernel<<<dim3(H_, B_), 256>>>(q, k, v, mask, ctx);

        gemm_tf32_kernel<<<gD, 256>>>(ctx, Wol, bo + l * D_, t, M_, D_, D_, 0, 1.0f);
        add_ln_kernel<<<M_, 256>>>(h, t, ln1_g + l * D_, ln1_b + l * D_, h);

        gemm_tf32_kernel<<<gF, 256>>>(h, W1l, b1 + l * F_, f, M_, F_, D_, 1, 1.0f);
        gemm_tf32_kernel<<<gD, 256>>>(f, W2l, b2 + l * D_, t, M_, D_, F_, 0, 1.0f);
        add_ln_kernel<<<M_, 256>>>(h, t, ln2_g + l * D_, ln2_b + l * D_, h);
    }

    cls_kernel<<<1, 256>>>(h, clsW, clsb, (float*)d_out);
}